// round 11
// baseline (speedup 1.0000x reference)
#include <cuda_runtime.h>
#include <cuda_bf16.h>
#include <cuda_fp16.h>
#include <cstdint>

// Problem constants (fixed by the dataset)
#define KDIM 256      // IN_DIM
#define UDIM 128      // UNITS
#define MAX_NODES 100000
#define MAX_EDGES 3200000

#define CSR_BLKS  96
#define SCATTER_CH 8192

// ---------------- device scratch (static globals: no runtime alloc) ----------
__device__ __half             g_h[(size_t)MAX_NODES * UDIM];   // 25.6 MB (fp16)
__device__ int                g_cnt[MAX_NODES];                // zero-init; self-zeroing
__device__ int                g_off[MAX_NODES + 1];
__device__ int                g_cur[MAX_NODES];
__device__ int                g_bsum[256];
__device__ unsigned long long g_cv[MAX_EDGES];                 // packed (col, val)
__device__ int                g_bar[2];   // CSR-only barriers (self-reset)
__device__ int                g_dep[2];
__device__ int                g_hist;     // hist arrivals   (reset at exit)
__device__ int                g_wq;       // scatter queue   (reset at exit)
__device__ int                g_done;     // exit counter    (reset at exit)
__device__ int                g_ready;    // CSR ready flag  (reset at exit)

// ---------------- small helpers ----------------------------------------------
__device__ __forceinline__ uint32_t smem_u32(const void* p) {
    uint32_t a;
    asm("{ .reg .u64 t; cvta.to.shared.u64 t, %1; cvt.u32.u64 %0, t; }"
        : "=r"(a) : "l"(p));
    return a;
}

__device__ __forceinline__ void ldmatrix_x4(uint32_t& r0, uint32_t& r1,
                                            uint32_t& r2, uint32_t& r3,
                                            uint32_t addr)
{
    asm volatile("ldmatrix.sync.aligned.m8n8.x4.shared.b16 {%0,%1,%2,%3}, [%4];"
                 : "=r"(r0), "=r"(r1), "=r"(r2), "=r"(r3) : "r"(addr));
}

__device__ __forceinline__ void mma_bf16(float* d, const uint32_t* a,
                                         uint32_t b0, uint32_t b1)
{
    asm volatile(
        "mma.sync.aligned.m16n8k16.row.col.f32.bf16.bf16.f32 "
        "{%0,%1,%2,%3}, {%4,%5,%6,%7}, {%8,%9}, {%0,%1,%2,%3};"
        : "+f"(d[0]), "+f"(d[1]), "+f"(d[2]), "+f"(d[3])
        : "r"(a[0]), "r"(a[1]), "r"(a[2]), "r"(a[3]), "r"(b0), "r"(b1));
}

__device__ __forceinline__ int ld_acq(const int* p) {
    int v;
    asm volatile("ld.acquire.gpu.b32 %0, [%1];" : "=r"(v) : "l"(p) : "memory");
    return v;
}

// Inter-block barrier among the 96 CSR blocks only (blocks 0..95 are in the
// first dispatch wave: 96 <= 148 SMs even at 1 CTA/SM). Self-resetting.
__device__ __forceinline__ void csr_barrier(int k)
{
    __threadfence();
    __syncthreads();
    if (threadIdx.x == 0) {
        atomicAdd(&g_bar[k], 1);
        while (ld_acq(&g_bar[k]) < CSR_BLKS) __nanosleep(128);
        int d = atomicAdd(&g_dep[k], 1);
        if (d == CSR_BLKS - 1) {
            atomicExch(&g_dep[k], 0);
            atomicExch(&g_bar[k], 0);
        }
    }
    __syncthreads();
}

// Chunked scatter work queue (any block can participate; idempotent exit).
__device__ __forceinline__ void scatter_wq(const int* __restrict__ rows,
                                           const int* __restrict__ cols,
                                           const float* __restrict__ vals,
                                           int E, int* s_chunk)
{
    const int tid = threadIdx.x;
    const int nch = (E + SCATTER_CH - 1) / SCATTER_CH;
    while (true) {
        __syncthreads();
        if (tid == 0) *s_chunk = atomicAdd(&g_wq, 1);
        __syncthreads();
        int c = *s_chunk;
        if (c >= nch) break;
        int base = c * SCATTER_CH;
        int end  = min(base + SCATTER_CH, E);
        for (int i = base + tid; i < end; i += 256) {
            int r = rows[i];
            int p = atomicAdd(&g_cur[r], 1);
            unsigned long long packed =
                (unsigned long long)(unsigned)cols[i] |
                ((unsigned long long)__float_as_uint(vals[i]) << 32);
            g_cv[p] = packed;
        }
    }
}

// ============================================================================
// FUSED kernel (grid = CSR_BLKS + gemm_nb = 878, non-persistent GEMM blocks):
//   ALL blocks:   histogram slice (chip-wide) -> arrive on g_hist
//   CSR  (0..95): wait all-hist -> distributed scan -> ready -> scatter queue
//   GEMM (rest):  one MMA tile -> non-blocking ready check -> help scatter
// No block ever spin-waits on work produced by an unscheduled block.
// ============================================================================
#define PITCH 80

__global__ __launch_bounds__(256) void fused_kernel(
    const float* __restrict__ X, const float* __restrict__ W,
    const int* __restrict__ rows, const int* __restrict__ cols,
    const float* __restrict__ vals, int M, int E)
{
    __shared__ __align__(16) char sA_hi[128 * PITCH];
    __shared__ __align__(16) char sA_lo[128 * PITCH];
    __shared__ __align__(16) char sB_hi[128 * PITCH];
    __shared__ __align__(16) char sB_lo[128 * PITCH];
    __shared__ int wsum[8];
    __shared__ int s_chunk;
    __shared__ int s_flag;

    const int tid  = threadIdx.x;
    const int bid  = blockIdx.x;
    const int nblk = gridDim.x;

    // ---- prologue (ALL blocks): histogram slice, then arrive
    for (int i = bid * 256 + tid; i < E; i += nblk * 256)
        atomicAdd(&g_cnt[rows[i]], 1);
    __threadfence();
    __syncthreads();
    if (tid == 0) atomicAdd(&g_hist, 1);

    if (bid < CSR_BLKS) {
        // ================= CSR role =================
        // Safe spin: every other block arrives on g_hist without waiting on
        // anything, so this is satisfiable regardless of occupancy.
        if (tid == 0)
            while (ld_acq(&g_hist) < nblk) __nanosleep(256);
        __syncthreads();

        // ---- distributed exclusive scan of g_cnt across 96 blocks
        const int C   = (M + CSR_BLKS - 1) / CSR_BLKS;   // 1042
        const int IPT = (C + 255) >> 8;                  // 5 (<=8)
        const int bstart = bid * C;
        const int bend   = min(bstart + C, M);
        const int i0     = bstart + tid * IPT;

        int loc[8];
        int s = 0;
#pragma unroll 8
        for (int j = 0; j < 8; j++) {
            int i = i0 + j;
            int v = (j < IPT && i < bend) ? g_cnt[i] : 0;
            loc[j] = v;
            s += v;
        }
        const int lane = tid & 31, w = tid >> 5;
        int p = s;
#pragma unroll
        for (int off = 1; off < 32; off <<= 1) {
            int t2 = __shfl_up_sync(0xffffffffu, p, off);
            if (lane >= off) p += t2;
        }
        if (lane == 31) wsum[w] = p;
        __syncthreads();
        if (w == 0) {
            int q = (lane < 8) ? wsum[lane] : 0;
#pragma unroll
            for (int off = 1; off < 8; off <<= 1) {
                int t2 = __shfl_up_sync(0xffffffffu, q, off);
                if (lane >= off) q += t2;
            }
            if (lane < 8) wsum[lane] = q;
        }
        __syncthreads();
        int excl  = (p - s) + ((w > 0) ? wsum[w - 1] : 0);
        int total = wsum[7];
        if (tid == 0) g_bsum[bid] = total;

        csr_barrier(0);

        int* red = (int*)sA_hi;
        int v = (tid < bid) ? g_bsum[tid] : 0;
        red[tid] = v;
        __syncthreads();
#pragma unroll
        for (int st = 128; st > 0; st >>= 1) {
            if (tid < st) red[tid] += red[tid + st];
            __syncthreads();
        }
        int run = red[0] + excl;

#pragma unroll 8
        for (int j = 0; j < 8; j++) {
            int i = i0 + j;
            if (j < IPT && i < bend) {
                run += loc[j];
                g_off[i + 1] = run;
                g_cur[i]     = run - loc[j];
                g_cnt[i]     = 0;          // self-zero for next replay
            }
        }
        if (bid == 0 && tid == 0) g_off[0] = 0;

        csr_barrier(1);
        if (bid == 0 && tid == 0) {
            asm volatile("st.release.gpu.b32 [%0], %1;"
                         :: "l"(&g_ready), "r"(1) : "memory");
        }

        scatter_wq(rows, cols, vals, E, &s_chunk);
    } else {
        // ================= GEMM role: one tile, then opportunistic help ======
        const int wid  = tid >> 5;
        const int lane = tid & 31;
        const int warpM = wid & 3;
        const int warpN = wid >> 2;
        const int block_row = (bid - CSR_BLKS) * 128;

        const int matIdx = lane >> 3;
        const int rowInMat = lane & 7;
        const int a_roff = rowInMat + (matIdx & 1) * 8;
        const int a_koff = (matIdx >> 1) * 8;
        const int b_noff = (matIdx >> 1) * 8 + rowInMat;
        const int b_koff = (matIdx & 1) * 8;

        const uint32_t sAhi = smem_u32(sA_hi);
        const uint32_t sAlo = smem_u32(sA_lo);
        const uint32_t sBhi = smem_u32(sB_hi);
        const uint32_t sBlo = smem_u32(sB_lo);

        const int ld_row  = tid >> 1;
        const int ld_half = tid & 1;
        const int b_n  = tid >> 1;
        const int b_k0 = (tid & 1) * 16;

        float acc[2][8][4];
#pragma unroll
        for (int mg = 0; mg < 2; mg++)
#pragma unroll
            for (int ng = 0; ng < 8; ng++)
#pragma unroll
                for (int q = 0; q < 4; q++) acc[mg][ng][q] = 0.0f;

#pragma unroll 1
        for (int kc = 0; kc < KDIM; kc += 32) {
            // ---- A: load 16 fp32, split hi/lo, store bf16
            {
                int grow = block_row + ld_row;
                float f[16];
                if (grow < M) {
                    const float4* xp = (const float4*)(X + (size_t)grow * KDIM + kc + ld_half * 16);
#pragma unroll
                    for (int q = 0; q < 4; q++) {
                        float4 vv = xp[q];
                        f[q * 4 + 0] = vv.x; f[q * 4 + 1] = vv.y;
                        f[q * 4 + 2] = vv.z; f[q * 4 + 3] = vv.w;
                    }
                } else {
#pragma unroll
                    for (int q = 0; q < 16; q++) f[q] = 0.0f;
                }
                union { __nv_bfloat16 b[16]; uint4 u[2]; } hi, lo;
#pragma unroll
                for (int q = 0; q < 16; q++) {
                    __nv_bfloat16 h = __float2bfloat16(f[q]);
                    hi.b[q] = h;
                    lo.b[q] = __float2bfloat16(f[q] - __bfloat162float(h));
                }
                char* pa = sA_hi + ld_row * PITCH + ld_half * 32;
                char* pl = sA_lo + ld_row * PITCH + ld_half * 32;
                *(uint4*)(pa)      = hi.u[0];
                *(uint4*)(pa + 16) = hi.u[1];
                *(uint4*)(pl)      = lo.u[0];
                *(uint4*)(pl + 16) = lo.u[1];
            }
            // ---- B: load W fp32, split hi/lo + transpose to K-major
            {
                union { __nv_bfloat16 b[16]; uint4 u[2]; } hi, lo;
#pragma unroll
                for (int j = 0; j < 16; j++) {
                    float wv = W[(size_t)(kc + b_k0 + j) * UDIM + b_n];
                    __nv_bfloat16 h = __float2bfloat16(wv);
                    hi.b[j] = h;
                    lo.b[j] = __float2bfloat16(wv - __bfloat162float(h));
                }
                char* ph = sB_hi + b_n * PITCH + b_k0 * 2;
                char* pl = sB_lo + b_n * PITCH + b_k0 * 2;
                *(uint4*)(ph)      = hi.u[0];
                *(uint4*)(ph + 16) = hi.u[1];
                *(uint4*)(pl)      = lo.u[0];
                *(uint4*)(pl + 16) = lo.u[1];
            }
            __syncthreads();

#pragma unroll
            for (int ks = 0; ks < 2; ks++) {
                const int k0 = ks * 16;
                uint32_t ah[2][4], al[2][4];
#pragma unroll
                for (int mg = 0; mg < 2; mg++) {
                    int row = warpM * 32 + mg * 16 + a_roff;
                    uint32_t off = (uint32_t)(row * PITCH + (k0 + a_koff) * 2);
                    ldmatrix_x4(ah[mg][0], ah[mg][1], ah[mg][2], ah[mg][3], sAhi + off);
                    ldmatrix_x4(al[mg][0], al[mg][1], al[mg][2], al[mg][3], sAlo + off);
                }
#pragma unroll
                for (int g = 0; g < 4; g++) {
                    uint32_t bh4[4], bl4[4];
                    int n = warpN * 64 + g * 16 + b_noff;
                    uint32_t off = (uint32_t)(n * PITCH + (k0 + b_koff) * 2);
                    ldmatrix_x4(bh4[0], bh4[1], bh4[2], bh4[3], sBhi + off);
                    ldmatrix_x4(bl4[0], bl4[1], bl4[2], bl4[3], sBlo + off);
#pragma unroll
                    for (int mg = 0; mg < 2; mg++) {
#pragma unroll
                        for (int sg = 0; sg < 2; sg++) {
                            float* a = acc[mg][g * 2 + sg];
                            mma_bf16(a, ah[mg], bh4[sg * 2], bh4[sg * 2 + 1]); // hi*hi
                            mma_bf16(a, al[mg], bh4[sg * 2], bh4[sg * 2 + 1]); // lo*hi
                            mma_bf16(a, ah[mg], bl4[sg * 2], bl4[sg * 2 + 1]); // hi*lo
                        }
                    }
                }
            }
            __syncthreads();
        }

        // ---- epilogue: write h as fp16
        const int qrow = lane >> 2;
        const int qcol = (lane & 3) * 2;
#pragma unroll
        for (int mg = 0; mg < 2; mg++) {
#pragma unroll
            for (int ng = 0; ng < 8; ng++) {
                int col = warpN * 64 + ng * 8 + qcol;
                int r0 = block_row + warpM * 32 + mg * 16 + qrow;
                if (r0 < M)
                    *(__half2*)(g_h + (size_t)r0 * UDIM + col) =
                        __floats2half2_rn(acc[mg][ng][0], acc[mg][ng][1]);
                int r1 = r0 + 8;
                if (r1 < M)
                    *(__half2*)(g_h + (size_t)r1 * UDIM + col) =
                        __floats2half2_rn(acc[mg][ng][2], acc[mg][ng][3]);
            }
        }

        // ---- non-blocking: if CSR scan already done, help drain the scatter
        if (tid == 0) s_flag = ld_acq(&g_ready);
        __syncthreads();
        if (s_flag) scatter_wq(rows, cols, vals, E, &s_chunk);
    }

    // ---- exit accounting: last of ALL blocks resets counters for next replay
    __threadfence();
    __syncthreads();
    if (tid == 0) {
        int d = atomicAdd(&g_done, 1);
        if (d == nblk - 1) {
            atomicExch(&g_hist, 0);
            atomicExch(&g_wq, 0);
            atomicExch(&g_ready, 0);
            atomicExch(&g_done, 0);
        }
    }
}

// ============================================================================
// Segment reduce: one warp per output row, fp16 h gathers, fp32 accum
// ============================================================================
__global__ void reduce_kernel(float* __restrict__ out, int M)
{
    int warp = (blockIdx.x * blockDim.x + threadIdx.x) >> 5;
    int lane = threadIdx.x & 31;
    if (warp >= M) return;

    int s = g_off[warp];
    int e = g_off[warp + 1];

    float4 acc = make_float4(0.f, 0.f, 0.f, 0.f);
    int i = s;
    for (; i + 3 < e; i += 4) {
        unsigned long long p0 = __ldg(&g_cv[i]);
        unsigned long long p1 = __ldg(&g_cv[i + 1]);
        unsigned long long p2 = __ldg(&g_cv[i + 2]);
        unsigned long long p3 = __ldg(&g_cv[i + 3]);
        int c0 = (int)(unsigned)(p0 & 0xffffffffu);
        int c1 = (int)(unsigned)(p1 & 0xffffffffu);
        int c2 = (int)(unsigned)(p2 & 0xffffffffu);
        int c3 = (int)(unsigned)(p3 & 0xffffffffu);
        float v0 = __uint_as_float((unsigned)(p0 >> 32));
        float v1 = __uint_as_float((unsigned)(p1 >> 32));
        float v2 = __uint_as_float((unsigned)(p2 >> 32));
        float v3 = __uint_as_float((unsigned)(p3 >> 32));
        uint2 u0 = ((const uint2*)(g_h + (size_t)c0 * UDIM))[lane];
        uint2 u1 = ((const uint2*)(g_h + (size_t)c1 * UDIM))[lane];
        uint2 u2 = ((const uint2*)(g_h + (size_t)c2 * UDIM))[lane];
        uint2 u3 = ((const uint2*)(g_h + (size_t)c3 * UDIM))[lane];
        float2 a0 = __half22float2(*(__half2*)&u0.x);
        float2 b0 = __half22float2(*(__half2*)&u0.y);
        float2 a1 = __half22float2(*(__half2*)&u1.x);
        float2 b1 = __half22float2(*(__half2*)&u1.y);
        float2 a2 = __half22float2(*(__half2*)&u2.x);
        float2 b2 = __half22float2(*(__half2*)&u2.y);
        float2 a3 = __half22float2(*(__half2*)&u3.x);
        float2 b3 = __half22float2(*(__half2*)&u3.y);
        acc.x = fmaf(v0, a0.x, acc.x); acc.y = fmaf(v0, a0.y, acc.y);
        acc.z = fmaf(v0, b0.x, acc.z); acc.w = fmaf(v0, b0.y, acc.w);
        acc.x = fmaf(v1, a1.x, acc.x); acc.y = fmaf(v1, a1.y, acc.y);
        acc.z = fmaf(v1, b1.x, acc.z); acc.w = fmaf(v1, b1.y, acc.w);
        acc.x = fmaf(v2, a2.x, acc.x); acc.y = fmaf(v2, a2.y, acc.y);
        acc.z = fmaf(v2, b2.x, acc.z); acc.w = fmaf(v2, b2.y, acc.w);
        acc.x = fmaf(v3, a3.x, acc.x); acc.y = fmaf(v3, a3.y, acc.y);
        acc.z = fmaf(v3, b3.x, acc.z); acc.w = fmaf(v3, b3.y, acc.w);
    }
    for (; i < e; i++) {
        unsigned long long p0 = __ldg(&g_cv[i]);
        int c0 = (int)(unsigned)(p0 & 0xffffffffu);
        float v0 = __uint_as_float((unsigned)(p0 >> 32));
        uint2 u0 = ((const uint2*)(g_h + (size_t)c0 * UDIM))[lane];
        float2 a0 = __half22float2(*(__half2*)&u0.x);
        float2 b0 = __half22float2(*(__half2*)&u0.y);
        acc.x = fmaf(v0, a0.x, acc.x); acc.y = fmaf(v0, a0.y, acc.y);
        acc.z = fmaf(v0, b0.x, acc.z); acc.w = fmaf(v0, b0.y, acc.w);
    }

    acc.x = fmaxf(acc.x, 0.f); acc.y = fmaxf(acc.y, 0.f);
    acc.z = fmaxf(acc.z, 0.f); acc.w = fmaxf(acc.w, 0.f);

    ((float4*)(out + (size_t)warp * UDIM))[lane] = acc;
}

// ============================================================================
// launch
// ============================================================================
extern "C" void kernel_launch(void* const* d_in, const int* in_sizes, int n_in,
                              void* d_out, int out_size)
{
    const float* x      = (const float*)d_in[0];  // [M, 256]
    const float* kernel = (const float*)d_in[1];  // [256, 128]
    const int*   arows  = (const int*)d_in[2];    // [E]
    const int*   acols  = (const int*)d_in[3];    // [E]
    const float* avals  = (const float*)d_in[4];  // [E]
    float*       out    = (float*)d_out;          // [M, 128]

    const int M = in_sizes[0] / KDIM;
    const int E = in_sizes[2];
    const int gemm_nb = (M + 127) / 128;

    // 1) ONE fused kernel: chip-wide hist (all 878 blocks) -> CSR scan on
    //    wave-1 blocks -> scatter queue drained by CSR + finished GEMM blocks
    fused_kernel<<<CSR_BLKS + gemm_nb, 256>>>(x, kernel, arows, acols, avals, M, E);

    // 2) segment reduce + relu (fp16 gathers)
    reduce_kernel<<<(M * 32 + 255) / 256, 256>>>(out, M);
}

// round 12
// speedup vs baseline: 1.7835x; 1.7835x over previous
#include <cuda_runtime.h>
#include <cuda_bf16.h>
#include <cuda_fp16.h>
#include <cstdint>

// Problem constants (fixed by the dataset)
#define KDIM 256      // IN_DIM
#define UDIM 128      // UNITS
#define MAX_NODES 100000
#define MAX_EDGES 3200000

#define CSR_BLKS  96
#define HIST_CH   16384
#define SCATTER_CH 8192

// ---------------- device scratch (static globals: no runtime alloc) ----------
__device__ __half             g_h[(size_t)MAX_NODES * UDIM];   // 25.6 MB (fp16)
__device__ int                g_cnt[MAX_NODES];                // zero-init; self-zeroing
__device__ int                g_off[MAX_NODES + 1];
__device__ int                g_cur[MAX_NODES];
__device__ int                g_bsum[256];
__device__ unsigned long long g_cv[MAX_EDGES];                 // packed (col, val)
__device__ int                g_bar[2];   // CSR-only barriers (self-reset)
__device__ int                g_dep[2];
__device__ int                g_hq;       // hist chunk ticket queue (reset at exit)
__device__ int                g_hdone;    // hist chunks completed   (reset at exit)
__device__ int                g_wq;       // scatter queue           (reset at exit)
__device__ int                g_done;     // exit counter            (reset at exit)
__device__ int                g_ready;    // CSR ready flag          (reset at exit)

// ---------------- small helpers ----------------------------------------------
__device__ __forceinline__ uint32_t smem_u32(const void* p) {
    uint32_t a;
    asm("{ .reg .u64 t; cvta.to.shared.u64 t, %1; cvt.u32.u64 %0, t; }"
        : "=r"(a) : "l"(p));
    return a;
}

__device__ __forceinline__ void ldmatrix_x4(uint32_t& r0, uint32_t& r1,
                                            uint32_t& r2, uint32_t& r3,
                                            uint32_t addr)
{
    asm volatile("ldmatrix.sync.aligned.m8n8.x4.shared.b16 {%0,%1,%2,%3}, [%4];"
                 : "=r"(r0), "=r"(r1), "=r"(r2), "=r"(r3) : "r"(addr));
}

__device__ __forceinline__ void mma_bf16(float* d, const uint32_t* a,
                                         uint32_t b0, uint32_t b1)
{
    asm volatile(
        "mma.sync.aligned.m16n8k16.row.col.f32.bf16.bf16.f32 "
        "{%0,%1,%2,%3}, {%4,%5,%6,%7}, {%8,%9}, {%0,%1,%2,%3};"
        : "+f"(d[0]), "+f"(d[1]), "+f"(d[2]), "+f"(d[3])
        : "r"(a[0]), "r"(a[1]), "r"(a[2]), "r"(a[3]), "r"(b0), "r"(b1));
}

__device__ __forceinline__ int ld_acq(const int* p) {
    int v;
    asm volatile("ld.acquire.gpu.b32 %0, [%1];" : "=r"(v) : "l"(p) : "memory");
    return v;
}

// Inter-block barrier among the 96 CSR blocks only (blocks 0..95 are in the
// first dispatch wave: 96 <= 148 SMs even at 1 CTA/SM). Self-resetting.
__device__ __forceinline__ void csr_barrier(int k)
{
    __threadfence();
    __syncthreads();
    if (threadIdx.x == 0) {
        atomicAdd(&g_bar[k], 1);
        while (ld_acq(&g_bar[k]) < CSR_BLKS) __nanosleep(128);
        int d = atomicAdd(&g_dep[k], 1);
        if (d == CSR_BLKS - 1) {
            atomicExch(&g_dep[k], 0);
            atomicExch(&g_bar[k], 0);
        }
    }
    __syncthreads();
}

// Hist chunk queue: any block drains; returns # chunks this block completed.
// Progress never depends on unscheduled blocks (CSR blocks drain it too).
__device__ __forceinline__ int hist_drain(const int* __restrict__ rows,
                                          int E, int* s_chunk)
{
    const int tid = threadIdx.x;
    const int nch = (E + HIST_CH - 1) / HIST_CH;
    int done = 0;
    while (true) {
        __syncthreads();
        if (tid == 0) *s_chunk = atomicAdd(&g_hq, 1);
        __syncthreads();
        int c = *s_chunk;
        if (c >= nch) break;
        int base = c * HIST_CH;
        int end  = min(base + HIST_CH, E);
        for (int i = base + tid; i < end; i += 256)
            atomicAdd(&g_cnt[rows[i]], 1);
        done++;
    }
    return done;
}

// Chunked scatter work queue (any block can participate).
__device__ __forceinline__ void scatter_wq(const int* __restrict__ rows,
                                           const int* __restrict__ cols,
                                           const float* __restrict__ vals,
                                           int E, int* s_chunk)
{
    const int tid = threadIdx.x;
    const int nch = (E + SCATTER_CH - 1) / SCATTER_CH;
    while (true) {
        __syncthreads();
        if (tid == 0) *s_chunk = atomicAdd(&g_wq, 1);
        __syncthreads();
        int c = *s_chunk;
        if (c >= nch) break;
        int base = c * SCATTER_CH;
        int end  = min(base + SCATTER_CH, E);
        for (int i = base + tid; i < end; i += 256) {
            int r = rows[i];
            int p = atomicAdd(&g_cur[r], 1);
            unsigned long long packed =
                (unsigned long long)(unsigned)cols[i] |
                ((unsigned long long)__float_as_uint(vals[i]) << 32);
            g_cv[p] = packed;
        }
    }
}

// ============================================================================
// FUSED kernel (grid = CSR_BLKS + gemm_nb):
//   ALL blocks:   drain hist chunk queue (wave-1 does ~all of it, chip-wide)
//   CSR  (0..95): wait hist-chunks-done -> distributed scan -> ready -> scatter
//   GEMM (rest):  one MMA tile -> non-blocking ready check -> help scatter
// CSR's wait is on CHUNK COMPLETION, and CSR blocks drain the queue themselves
// -> satisfiable regardless of scheduling. No deadlock possible.
// ============================================================================
#define PITCH 80

__global__ __launch_bounds__(256) void fused_kernel(
    const float* __restrict__ X, const float* __restrict__ W,
    const int* __restrict__ rows, const int* __restrict__ cols,
    const float* __restrict__ vals, int M, int E)
{
    __shared__ __align__(16) char sA_hi[128 * PITCH];
    __shared__ __align__(16) char sA_lo[128 * PITCH];
    __shared__ __align__(16) char sB_hi[128 * PITCH];
    __shared__ __align__(16) char sB_lo[128 * PITCH];
    __shared__ int wsum[8];
    __shared__ int s_chunk;
    __shared__ int s_flag;

    const int tid  = threadIdx.x;
    const int bid  = blockIdx.x;
    const int nblk = gridDim.x;
    const int hist_nch = (E + HIST_CH - 1) / HIST_CH;

    // ---- prologue (ALL blocks): drain hist chunk queue, report completions
    int hc = hist_drain(rows, E, &s_chunk);
    __threadfence();                   // every thread: publish its atomics
    __syncthreads();
    if (tid == 0 && hc) atomicAdd(&g_hdone, hc);

    if (bid < CSR_BLKS) {
        // ================= CSR role =================
        // Safe spin: the hist queue is drained by wave-1 blocks including
        // the CSR blocks themselves -> g_hdone reaches hist_nch regardless
        // of whether any GEMM block ever runs.
        if (tid == 0)
            while (ld_acq(&g_hdone) < hist_nch) __nanosleep(256);
        __syncthreads();

        // ---- distributed exclusive scan of g_cnt across 96 blocks
        const int C   = (M + CSR_BLKS - 1) / CSR_BLKS;   // 1042
        const int IPT = (C + 255) >> 8;                  // 5 (<=8)
        const int bstart = bid * C;
        const int bend   = min(bstart + C, M);
        const int i0     = bstart + tid * IPT;

        int loc[8];
        int s = 0;
#pragma unroll 8
        for (int j = 0; j < 8; j++) {
            int i = i0 + j;
            int v = (j < IPT && i < bend) ? g_cnt[i] : 0;
            loc[j] = v;
            s += v;
        }
        const int lane = tid & 31, w = tid >> 5;
        int p = s;
#pragma unroll
        for (int off = 1; off < 32; off <<= 1) {
            int t2 = __shfl_up_sync(0xffffffffu, p, off);
            if (lane >= off) p += t2;
        }
        if (lane == 31) wsum[w] = p;
        __syncthreads();
        if (w == 0) {
            int q = (lane < 8) ? wsum[lane] : 0;
#pragma unroll
            for (int off = 1; off < 8; off <<= 1) {
                int t2 = __shfl_up_sync(0xffffffffu, q, off);
                if (lane >= off) q += t2;
            }
            if (lane < 8) wsum[lane] = q;
        }
        __syncthreads();
        int excl  = (p - s) + ((w > 0) ? wsum[w - 1] : 0);
        int total = wsum[7];
        if (tid == 0) g_bsum[bid] = total;

        csr_barrier(0);

        int* red = (int*)sA_hi;
        int v = (tid < bid) ? g_bsum[tid] : 0;
        red[tid] = v;
        __syncthreads();
#pragma unroll
        for (int st = 128; st > 0; st >>= 1) {
            if (tid < st) red[tid] += red[tid + st];
            __syncthreads();
        }
        int run = red[0] + excl;

#pragma unroll 8
        for (int j = 0; j < 8; j++) {
            int i = i0 + j;
            if (j < IPT && i < bend) {
                run += loc[j];
                g_off[i + 1] = run;
                g_cur[i]     = run - loc[j];
                g_cnt[i]     = 0;          // self-zero for next replay
            }
        }
        if (bid == 0 && tid == 0) g_off[0] = 0;

        csr_barrier(1);
        if (bid == 0 && tid == 0) {
            asm volatile("st.release.gpu.b32 [%0], %1;"
                         :: "l"(&g_ready), "r"(1) : "memory");
        }

        scatter_wq(rows, cols, vals, E, &s_chunk);
    } else {
        // ================= GEMM role: one tile, then opportunistic help ======
        const int wid  = tid >> 5;
        const int lane = tid & 31;
        const int warpM = wid & 3;
        const int warpN = wid >> 2;
        const int block_row = (bid - CSR_BLKS) * 128;

        const int matIdx = lane >> 3;
        const int rowInMat = lane & 7;
        const int a_roff = rowInMat + (matIdx & 1) * 8;
        const int a_koff = (matIdx >> 1) * 8;
        const int b_noff = (matIdx >> 1) * 8 + rowInMat;
        const int b_koff = (matIdx & 1) * 8;

        const uint32_t sAhi = smem_u32(sA_hi);
        const uint32_t sAlo = smem_u32(sA_lo);
        const uint32_t sBhi = smem_u32(sB_hi);
        const uint32_t sBlo = smem_u32(sB_lo);

        const int ld_row  = tid >> 1;
        const int ld_half = tid & 1;
        const int b_n  = tid >> 1;
        const int b_k0 = (tid & 1) * 16;

        float acc[2][8][4];
#pragma unroll
        for (int mg = 0; mg < 2; mg++)
#pragma unroll
            for (int ng = 0; ng < 8; ng++)
#pragma unroll
                for (int q = 0; q < 4; q++) acc[mg][ng][q] = 0.0f;

#pragma unroll 1
        for (int kc = 0; kc < KDIM; kc += 32) {
            // ---- A: load 16 fp32, split hi/lo, store bf16
            {
                int grow = block_row + ld_row;
                float f[16];
                if (grow < M) {
                    const float4* xp = (const float4*)(X + (size_t)grow * KDIM + kc + ld_half * 16);
#pragma unroll
                    for (int q = 0; q < 4; q++) {
                        float4 vv = xp[q];
                        f[q * 4 + 0] = vv.x; f[q * 4 + 1] = vv.y;
                        f[q * 4 + 2] = vv.z; f[q * 4 + 3] = vv.w;
                    }
                } else {
#pragma unroll
                    for (int q = 0; q < 16; q++) f[q] = 0.0f;
                }
                union { __nv_bfloat16 b[16]; uint4 u[2]; } hi, lo;
#pragma unroll
                for (int q = 0; q < 16; q++) {
                    __nv_bfloat16 h = __float2bfloat16(f[q]);
                    hi.b[q] = h;
                    lo.b[q] = __float2bfloat16(f[q] - __bfloat162float(h));
                }
                char* pa = sA_hi + ld_row * PITCH + ld_half * 32;
                char* pl = sA_lo + ld_row * PITCH + ld_half * 32;
                *(uint4*)(pa)      = hi.u[0];
                *(uint4*)(pa + 16) = hi.u[1];
                *(uint4*)(pl)      = lo.u[0];
                *(uint4*)(pl + 16) = lo.u[1];
            }
            // ---- B: load W fp32, split hi/lo + transpose to K-major
            {
                union { __nv_bfloat16 b[16]; uint4 u[2]; } hi, lo;
#pragma unroll
                for (int j = 0; j < 16; j++) {
                    float wv = W[(size_t)(kc + b_k0 + j) * UDIM + b_n];
                    __nv_bfloat16 h = __float2bfloat16(wv);
                    hi.b[j] = h;
                    lo.b[j] = __float2bfloat16(wv - __bfloat162float(h));
                }
                char* ph = sB_hi + b_n * PITCH + b_k0 * 2;
                char* pl = sB_lo + b_n * PITCH + b_k0 * 2;
                *(uint4*)(ph)      = hi.u[0];
                *(uint4*)(ph + 16) = hi.u[1];
                *(uint4*)(pl)      = lo.u[0];
                *(uint4*)(pl + 16) = lo.u[1];
            }
            __syncthreads();

#pragma unroll
            for (int ks = 0; ks < 2; ks++) {
                const int k0 = ks * 16;
                uint32_t ah[2][4], al[2][4];
#pragma unroll
                for (int mg = 0; mg < 2; mg++) {
                    int row = warpM * 32 + mg * 16 + a_roff;
                    uint32_t off = (uint32_t)(row * PITCH + (k0 + a_koff) * 2);
                    ldmatrix_x4(ah[mg][0], ah[mg][1], ah[mg][2], ah[mg][3], sAhi + off);
                    ldmatrix_x4(al[mg][0], al[mg][1], al[mg][2], al[mg][3], sAlo + off);
                }
#pragma unroll
                for (int g = 0; g < 4; g++) {
                    uint32_t bh4[4], bl4[4];
                    int n = warpN * 64 + g * 16 + b_noff;
                    uint32_t off = (uint32_t)(n * PITCH + (k0 + b_koff) * 2);
                    ldmatrix_x4(bh4[0], bh4[1], bh4[2], bh4[3], sBhi + off);
                    ldmatrix_x4(bl4[0], bl4[1], bl4[2], bl4[3], sBlo + off);
#pragma unroll
                    for (int mg = 0; mg < 2; mg++) {
#pragma unroll
                        for (int sg = 0; sg < 2; sg++) {
                            float* a = acc[mg][g * 2 + sg];
                            mma_bf16(a, ah[mg], bh4[sg * 2], bh4[sg * 2 + 1]); // hi*hi
                            mma_bf16(a, al[mg], bh4[sg * 2], bh4[sg * 2 + 1]); // lo*hi
                            mma_bf16(a, ah[mg], bl4[sg * 2], bl4[sg * 2 + 1]); // hi*lo
                        }
                    }
                }
            }
            __syncthreads();
        }

        // ---- epilogue: write h as fp16
        const int qrow = lane >> 2;
        const int qcol = (lane & 3) * 2;
#pragma unroll
        for (int mg = 0; mg < 2; mg++) {
#pragma unroll
            for (int ng = 0; ng < 8; ng++) {
                int col = warpN * 64 + ng * 8 + qcol;
                int r0 = block_row + warpM * 32 + mg * 16 + qrow;
                if (r0 < M)
                    *(__half2*)(g_h + (size_t)r0 * UDIM + col) =
                        __floats2half2_rn(acc[mg][ng][0], acc[mg][ng][1]);
                int r1 = r0 + 8;
                if (r1 < M)
                    *(__half2*)(g_h + (size_t)r1 * UDIM + col) =
                        __floats2half2_rn(acc[mg][ng][2], acc[mg][ng][3]);
            }
        }

        // ---- non-blocking: if CSR scan already done, help drain the scatter
        if (tid == 0) s_flag = ld_acq(&g_ready);
        __syncthreads();
        if (s_flag) scatter_wq(rows, cols, vals, E, &s_chunk);
    }

    // ---- exit accounting: last of ALL blocks resets counters for next replay
    __threadfence();
    __syncthreads();
    if (tid == 0) {
        int d = atomicAdd(&g_done, 1);
        if (d == nblk - 1) {
            atomicExch(&g_hq, 0);
            atomicExch(&g_hdone, 0);
            atomicExch(&g_wq, 0);
            atomicExch(&g_ready, 0);
            atomicExch(&g_done, 0);
        }
    }
}

// ============================================================================
// Segment reduce: one warp per output row, fp16 h gathers, fp32 accum
// ============================================================================
__global__ void reduce_kernel(float* __restrict__ out, int M)
{
    int warp = (blockIdx.x * blockDim.x + threadIdx.x) >> 5;
    int lane = threadIdx.x & 31;
    if (warp >= M) return;

    int s = g_off[warp];
    int e = g_off[warp + 1];

    float4 acc = make_float4(0.f, 0.f, 0.f, 0.f);
    int i = s;
    for (; i + 3 < e; i += 4) {
        unsigned long long p0 = __ldg(&g_cv[i]);
        unsigned long long p1 = __ldg(&g_cv[i + 1]);
        unsigned long long p2 = __ldg(&g_cv[i + 2]);
        unsigned long long p3 = __ldg(&g_cv[i + 3]);
        int c0 = (int)(unsigned)(p0 & 0xffffffffu);
        int c1 = (int)(unsigned)(p1 & 0xffffffffu);
        int c2 = (int)(unsigned)(p2 & 0xffffffffu);
        int c3 = (int)(unsigned)(p3 & 0xffffffffu);
        float v0 = __uint_as_float((unsigned)(p0 >> 32));
        float v1 = __uint_as_float((unsigned)(p1 >> 32));
        float v2 = __uint_as_float((unsigned)(p2 >> 32));
        float v3 = __uint_as_float((unsigned)(p3 >> 32));
        uint2 u0 = ((const uint2*)(g_h + (size_t)c0 * UDIM))[lane];
        uint2 u1 = ((const uint2*)(g_h + (size_t)c1 * UDIM))[lane];
        uint2 u2 = ((const uint2*)(g_h + (size_t)c2 * UDIM))[lane];
        uint2 u3 = ((const uint2*)(g_h + (size_t)c3 * UDIM))[lane];
        float2 a0 = __half22float2(*(__half2*)&u0.x);
        float2 b0 = __half22float2(*(__half2*)&u0.y);
        float2 a1 = __half22float2(*(__half2*)&u1.x);
        float2 b1 = __half22float2(*(__half2*)&u1.y);
        float2 a2 = __half22float2(*(__half2*)&u2.x);
        float2 b2 = __half22float2(*(__half2*)&u2.y);
        float2 a3 = __half22float2(*(__half2*)&u3.x);
        float2 b3 = __half22float2(*(__half2*)&u3.y);
        acc.x = fmaf(v0, a0.x, acc.x); acc.y = fmaf(v0, a0.y, acc.y);
        acc.z = fmaf(v0, b0.x, acc.z); acc.w = fmaf(v0, b0.y, acc.w);
        acc.x = fmaf(v1, a1.x, acc.x); acc.y = fmaf(v1, a1.y, acc.y);
        acc.z = fmaf(v1, b1.x, acc.z); acc.w = fmaf(v1, b1.y, acc.w);
        acc.x = fmaf(v2, a2.x, acc.x); acc.y = fmaf(v2, a2.y, acc.y);
        acc.z = fmaf(v2, b2.x, acc.z); acc.w = fmaf(v2, b2.y, acc.w);
        acc.x = fmaf(v3, a3.x, acc.x); acc.y = fmaf(v3, a3.y, acc.y);
        acc.z = fmaf(v3, b3.x, acc.z); acc.w = fmaf(v3, b3.y, acc.w);
    }
    for (; i < e; i++) {
        unsigned long long p0 = __ldg(&g_cv[i]);
        int c0 = (int)(unsigned)(p0 & 0xffffffffu);
        float v0 = __uint_as_float((unsigned)(p0 >> 32));
        uint2 u0 = ((const uint2*)(g_h + (size_t)c0 * UDIM))[lane];
        float2 a0 = __half22float2(*(__half2*)&u0.x);
        float2 b0 = __half22float2(*(__half2*)&u0.y);
        acc.x = fmaf(v0, a0.x, acc.x); acc.y = fmaf(v0, a0.y, acc.y);
        acc.z = fmaf(v0, b0.x, acc.z); acc.w = fmaf(v0, b0.y, acc.w);
    }

    acc.x = fmaxf(acc.x, 0.f); acc.y = fmaxf(acc.y, 0.f);
    acc.z = fmaxf(acc.z, 0.f); acc.w = fmaxf(acc.w, 0.f);

    ((float4*)(out + (size_t)warp * UDIM))[lane] = acc;
}

// ============================================================================
// launch
// ============================================================================
extern "C" void kernel_launch(void* const* d_in, const int* in_sizes, int n_in,
                              void* d_out, int out_size)
{
    const float* x      = (const float*)d_in[0];  // [M, 256]
    const float* kernel = (const float*)d_in[1];  // [256, 128]
    const int*   arows  = (const int*)d_in[2];    // [E]
    const int*   acols  = (const int*)d_in[3];    // [E]
    const float* avals  = (const float*)d_in[4];  // [E]
    float*       out    = (float*)d_out;          // [M, 128]

    const int M = in_sizes[0] / KDIM;
    const int E = in_sizes[2];
    const int gemm_nb = (M + 127) / 128;

    // 1) ONE fused kernel: hist chunk queue (drained chip-wide by wave-1),
    //    CSR scan on blocks 0..95, scatter queue helped by finished GEMM blocks
    fused_kernel<<<CSR_BLKS + gemm_nb, 256>>>(x, kernel, arows, acols, avals, M, E);

    // 2) segment reduce + relu (fp16 gathers)
    reduce_kernel<<<(M * 32 + 255) / 256, 256>>>(out, M);
}

// round 14
// speedup vs baseline: 1.8127x; 1.0164x over previous
#include <cuda_runtime.h>
#include <cuda_bf16.h>
#include <cuda_fp16.h>
#include <cstdint>

// Problem constants (fixed by the dataset)
#define KDIM 256      // IN_DIM
#define UDIM 128      // UNITS
#define MAX_NODES 100000
#define MAX_EDGES 3200000

#define CSR_BLKS 128
#define SCATTER_CH 8192

// ---------------- device scratch (static globals: no runtime alloc) ----------
__device__ __half             g_h[(size_t)MAX_NODES * UDIM];   // 25.6 MB (fp16)
__device__ int                g_cnt[MAX_NODES];                // zero-init; self-zeroing
__device__ int                g_off[MAX_NODES + 1];
__device__ int                g_cur[MAX_NODES];
__device__ int                g_bsum[256];
__device__ unsigned long long g_cv[MAX_EDGES];                 // packed (byteoff, val)
__device__ int                g_bar[3];   // CSR-only barriers (3 DISTINCT slots)
__device__ int                g_dep[3];
__device__ int                g_ready;    // CSR ready flag  (reset at exit)
__device__ int                g_wq;       // scatter queue   (reset at exit)
__device__ int                g_done;     // exit counter    (reset at exit)

// ---------------- small helpers ----------------------------------------------
__device__ __forceinline__ uint32_t smem_u32(const void* p) {
    uint32_t a;
    asm("{ .reg .u64 t; cvta.to.shared.u64 t, %1; cvt.u32.u64 %0, t; }"
        : "=r"(a) : "l"(p));
    return a;
}

__device__ __forceinline__ void ldmatrix_x4(uint32_t& r0, uint32_t& r1,
                                            uint32_t& r2, uint32_t& r3,
                                            uint32_t addr)
{
    asm volatile("ldmatrix.sync.aligned.m8n8.x4.shared.b16 {%0,%1,%2,%3}, [%4];"
                 : "=r"(r0), "=r"(r1), "=r"(r2), "=r"(r3) : "r"(addr));
}

__device__ __forceinline__ void mma_bf16(float* d, const uint32_t* a,
                                         uint32_t b0, uint32_t b1)
{
    asm volatile(
        "mma.sync.aligned.m16n8k16.row.col.f32.bf16.bf16.f32 "
        "{%0,%1,%2,%3}, {%4,%5,%6,%7}, {%8,%9}, {%0,%1,%2,%3};"
        : "+f"(d[0]), "+f"(d[1]), "+f"(d[2]), "+f"(d[3])
        : "r"(a[0]), "r"(a[1]), "r"(a[2]), "r"(a[3]), "r"(b0), "r"(b1));
}

__device__ __forceinline__ int ld_acq(const int* p) {
    int v;
    asm volatile("ld.acquire.gpu.b32 %0, [%1];" : "=r"(v) : "l"(p) : "memory");
    return v;
}

// Inter-block barrier among the CSR blocks only (blocks 0..127 are in the
// first dispatch wave: 128 <= 148 SMs even at 1 CTA/SM). Self-resetting.
// IMPORTANT: each use site must use a DISTINCT slot k — a slot cannot be
// reused back-to-back (reset races with a fast block's re-arrival).
__device__ __forceinline__ void csr_barrier(int k)
{
    __threadfence();
    __syncthreads();
    if (threadIdx.x == 0) {
        atomicAdd(&g_bar[k], 1);
        while (ld_acq(&g_bar[k]) < CSR_BLKS) __nanosleep(128);
        int d = atomicAdd(&g_dep[k], 1);
        if (d == CSR_BLKS - 1) {
            atomicExch(&g_dep[k], 0);
            atomicExch(&g_bar[k], 0);
        }
    }
    __syncthreads();
}

// Chunked scatter work queue (any block can participate).
// Packs (h-row byte offset = col*256) | (val bits << 32).
__device__ __forceinline__ void scatter_wq(const int* __restrict__ rows,
                                           const int* __restrict__ cols,
                                           const float* __restrict__ vals,
                                           int E, int* s_chunk)
{
    const int tid = threadIdx.x;
    const int nch = (E + SCATTER_CH - 1) / SCATTER_CH;
    while (true) {
        __syncthreads();
        if (tid == 0) *s_chunk = atomicAdd(&g_wq, 1);
        __syncthreads();
        int c = *s_chunk;
        if (c >= nch) break;
        int base = c * SCATTER_CH;
        int end  = min(base + SCATTER_CH, E);
        for (int i = base + tid; i < end; i += 256) {
            int r = rows[i];
            int p = atomicAdd(&g_cur[r], 1);
            unsigned long long packed =
                (unsigned long long)((unsigned)cols[i] << 8) |   // byte offset
                ((unsigned long long)__float_as_uint(vals[i]) << 32);
            g_cv[p] = packed;
        }
    }
}

// ============================================================================
// FUSED kernel (round-9 structure, CSR widened to 128 blocks):
//   blocks [0, CSR_BLKS):          hist -> bar0 -> scan -> bar1 -> off write
//                                  -> bar2 -> scatter queue
//   blocks [CSR_BLKS, +gemm_nb):   one GEMM tile (mma.sync bf16 hi/lo split)
// ============================================================================
#define PITCH 80

__global__ __launch_bounds__(256) void fused_kernel(
    const float* __restrict__ X, const float* __restrict__ W,
    const int* __restrict__ rows, const int* __restrict__ cols,
    const float* __restrict__ vals, int M, int E)
{
    __shared__ __align__(16) char sA_hi[128 * PITCH];
    __shared__ __align__(16) char sA_lo[128 * PITCH];
    __shared__ __align__(16) char sB_hi[128 * PITCH];
    __shared__ __align__(16) char sB_lo[128 * PITCH];
    __shared__ int wsum[8];
    __shared__ int s_chunk;

    const int tid = threadIdx.x;
    const int bid = blockIdx.x;

    if (bid < CSR_BLKS) {
        // ================= CSR role =================
        const int stride = CSR_BLKS * 256;

        // ---- phase 1: histogram (grid-stride over all edges)
        for (int i = bid * 256 + tid; i < E; i += stride)
            atomicAdd(&g_cnt[rows[i]], 1);

        csr_barrier(0);

        // ---- phase 2: distributed exclusive scan of g_cnt
        const int C   = (M + CSR_BLKS - 1) / CSR_BLKS;   // 782
        const int IPT = (C + 255) >> 8;                  // 4 (<=8)
        const int bstart = bid * C;
        const int bend   = min(bstart + C, M);
        const int i0     = bstart + tid * IPT;

        int loc[8];
        int s = 0;
#pragma unroll 8
        for (int j = 0; j < 8; j++) {
            int i = i0 + j;
            int v = (j < IPT && i < bend) ? g_cnt[i] : 0;
            loc[j] = v;
            s += v;
        }
        const int lane = tid & 31, w = tid >> 5;
        int p = s;
#pragma unroll
        for (int off = 1; off < 32; off <<= 1) {
            int t2 = __shfl_up_sync(0xffffffffu, p, off);
            if (lane >= off) p += t2;
        }
        if (lane == 31) wsum[w] = p;
        __syncthreads();
        if (w == 0) {
            int q = (lane < 8) ? wsum[lane] : 0;
#pragma unroll
            for (int off = 1; off < 8; off <<= 1) {
                int t2 = __shfl_up_sync(0xffffffffu, q, off);
                if (lane >= off) q += t2;
            }
            if (lane < 8) wsum[lane] = q;
        }
        __syncthreads();
        int excl  = (p - s) + ((w > 0) ? wsum[w - 1] : 0);
        int total = wsum[7];
        if (tid == 0) g_bsum[bid] = total;

        csr_barrier(1);

        int* red = (int*)sA_hi;
        int v = (tid < bid) ? g_bsum[tid] : 0;   // bid <= 127 < 256
        red[tid] = v;
        __syncthreads();
#pragma unroll
        for (int st = 128; st > 0; st >>= 1) {
            if (tid < st) red[tid] += red[tid + st];
            __syncthreads();
        }
        int run = red[0] + excl;

#pragma unroll 8
        for (int j = 0; j < 8; j++) {
            int i = i0 + j;
            if (j < IPT && i < bend) {
                run += loc[j];
                g_off[i + 1] = run;
                g_cur[i]     = run - loc[j];
                g_cnt[i]     = 0;          // self-zero for next replay
            }
        }
        if (bid == 0 && tid == 0) g_off[0] = 0;

        csr_barrier(2);
        if (bid == 0 && tid == 0) {
            asm volatile("st.release.gpu.b32 [%0], %1;"
                         :: "l"(&g_ready), "r"(1) : "memory");
        }

        // ---- phase 3: scatter via chunk queue
        scatter_wq(rows, cols, vals, E, &s_chunk);
    } else {
        // ================= GEMM role: one tile =================
        const int wid  = tid >> 5;
        const int lane = tid & 31;
        const int warpM = wid & 3;
        const int warpN = wid >> 2;
        const int block_row = (bid - CSR_BLKS) * 128;

        const int matIdx = lane >> 3;
        const int rowInMat = lane & 7;
        const int a_roff = rowInMat + (matIdx & 1) * 8;
        const int a_koff = (matIdx >> 1) * 8;
        const int b_noff = (matIdx >> 1) * 8 + rowInMat;
        const int b_koff = (matIdx & 1) * 8;

        const uint32_t sAhi = smem_u32(sA_hi);
        const uint32_t sAlo = smem_u32(sA_lo);
        const uint32_t sBhi = smem_u32(sB_hi);
        const uint32_t sBlo = smem_u32(sB_lo);

        const int ld_row  = tid >> 1;
        const int ld_half = tid & 1;
        const int b_n  = tid >> 1;
        const int b_k0 = (tid & 1) * 16;

        float acc[2][8][4];
#pragma unroll
        for (int mg = 0; mg < 2; mg++)
#pragma unroll
            for (int ng = 0; ng < 8; ng++)
#pragma unroll
                for (int q = 0; q < 4; q++) acc[mg][ng][q] = 0.0f;

#pragma unroll 1
        for (int kc = 0; kc < KDIM; kc += 32) {
            // ---- A: load 16 fp32, split hi/lo, store bf16
            {
                int grow = block_row + ld_row;
                float f[16];
                if (grow < M) {
                    const float4* xp = (const float4*)(X + (size_t)grow * KDIM + kc + ld_half * 16);
#pragma unroll
                    for (int q = 0; q < 4; q++) {
                        float4 vv = xp[q];
                        f[q * 4 + 0] = vv.x; f[q * 4 + 1] = vv.y;
                        f[q * 4 + 2] = vv.z; f[q * 4 + 3] = vv.w;
                    }
                } else {
#pragma unroll
                    for (int q = 0; q < 16; q++) f[q] = 0.0f;
                }
                union { __nv_bfloat16 b[16]; uint4 u[2]; } hi, lo;
#pragma unroll
                for (int q = 0; q < 16; q++) {
                    __nv_bfloat16 h = __float2bfloat16(f[q]);
                    hi.b[q] = h;
                    lo.b[q] = __float2bfloat16(f[q] - __bfloat162float(h));
                }
                char* pa = sA_hi + ld_row * PITCH + ld_half * 32;
                char* pl = sA_lo + ld_row * PITCH + ld_half * 32;
                *(uint4*)(pa)      = hi.u[0];
                *(uint4*)(pa + 16) = hi.u[1];
                *(uint4*)(pl)      = lo.u[0];
                *(uint4*)(pl + 16) = lo.u[1];
            }
            // ---- B: load W fp32, split hi/lo + transpose to K-major
            {
                union { __nv_bfloat16 b[16]; uint4 u[2]; } hi, lo;
#pragma unroll
                for (int j = 0; j < 16; j++) {
                    float wv = W[(size_t)(kc + b_k0 + j) * UDIM + b_n];
                    __nv_bfloat16 h = __float2bfloat16(wv);
                    hi.b[j] = h;
                    lo.b[j] = __float2bfloat16(wv - __bfloat162float(h));
                }
                char* ph = sB_hi + b_n * PITCH + b_k0 * 2;
                char* pl = sB_lo + b_n * PITCH + b_k0 * 2;
                *(uint4*)(ph)      = hi.u[0];
                *(uint4*)(ph + 16) = hi.u[1];
                *(uint4*)(pl)      = lo.u[0];
                *(uint4*)(pl + 16) = lo.u[1];
            }
            __syncthreads();

#pragma unroll
            for (int ks = 0; ks < 2; ks++) {
                const int k0 = ks * 16;
                uint32_t ah[2][4], al[2][4];
#pragma unroll
                for (int mg = 0; mg < 2; mg++) {
                    int row = warpM * 32 + mg * 16 + a_roff;
                    uint32_t off = (uint32_t)(row * PITCH + (k0 + a_koff) * 2);
                    ldmatrix_x4(ah[mg][0], ah[mg][1], ah[mg][2], ah[mg][3], sAhi + off);
                    ldmatrix_x4(al[mg][0], al[mg][1], al[mg][2], al[mg][3], sAlo + off);
                }
#pragma unroll
                for (int g = 0; g < 4; g++) {
                    uint32_t bh4[4], bl4[4];
                    int n = warpN * 64 + g * 16 + b_noff;
                    uint32_t off = (uint32_t)(n * PITCH + (k0 + b_koff) * 2);
                    ldmatrix_x4(bh4[0], bh4[1], bh4[2], bh4[3], sBhi + off);
                    ldmatrix_x4(bl4[0], bl4[1], bl4[2], bl4[3], sBlo + off);
#pragma unroll
                    for (int mg = 0; mg < 2; mg++) {
#pragma unroll
                        for (int sg = 0; sg < 2; sg++) {
                            float* a = acc[mg][g * 2 + sg];
                            mma_bf16(a, ah[mg], bh4[sg * 2], bh4[sg * 2 + 1]); // hi*hi
                            mma_bf16(a, al[mg], bh4[sg * 2], bh4[sg * 2 + 1]); // lo*hi
                            mma_bf16(a, ah[mg], bl4[sg * 2], bl4[sg * 2 + 1]); // hi*lo
                        }
                    }
                }
            }
            __syncthreads();
        }

        // ---- epilogue: write h as fp16
        const int qrow = lane >> 2;
        const int qcol = (lane & 3) * 2;
#pragma unroll
        for (int mg = 0; mg < 2; mg++) {
#pragma unroll
            for (int ng = 0; ng < 8; ng++) {
                int col = warpN * 64 + ng * 8 + qcol;
                int r0 = block_row + warpM * 32 + mg * 16 + qrow;
                if (r0 < M)
                    *(__half2*)(g_h + (size_t)r0 * UDIM + col) =
                        __floats2half2_rn(acc[mg][ng][0], acc[mg][ng][1]);
                int r1 = r0 + 8;
                if (r1 < M)
                    *(__half2*)(g_h + (size_t)r1 * UDIM + col) =
                        __floats2half2_rn(acc[mg][ng][2], acc[mg][ng][3]);
            }
        }
    }

    // ---- exit accounting: last block resets counters for next replay
    __threadfence();
    __syncthreads();
    if (tid == 0) {
        int d = atomicAdd(&g_done, 1);
        if (d == (int)gridDim.x - 1) {
            atomicExch(&g_wq, 0);
            atomicExch(&g_ready, 0);
            atomicExch(&g_done, 0);
        }
    }
}

// ============================================================================
// Segment reduce: one warp per output row, fp16 h gathers via packed byte
// offsets (no per-edge address multiply), fp32 accum, relu epilogue
// ============================================================================
__global__ void reduce_kernel(float* __restrict__ out, int M)
{
    int warp = (blockIdx.x * blockDim.x + threadIdx.x) >> 5;
    int lane = threadIdx.x & 31;
    if (warp >= M) return;

    int s = g_off[warp];
    int e = g_off[warp + 1];

    const char* hbase = (const char*)g_h + lane * 8;   // lane's 8-byte column slot

    float4 acc = make_float4(0.f, 0.f, 0.f, 0.f);
    int i = s;
    for (; i + 3 < e; i += 4) {
        unsigned long long p0 = __ldg(&g_cv[i]);
        unsigned long long p1 = __ldg(&g_cv[i + 1]);
        unsigned long long p2 = __ldg(&g_cv[i + 2]);
        unsigned long long p3 = __ldg(&g_cv[i + 3]);
        unsigned o0 = (unsigned)p0, o1 = (unsigned)p1;
        unsigned o2 = (unsigned)p2, o3 = (unsigned)p3;
        float v0 = __uint_as_float((unsigned)(p0 >> 32));
        float v1 = __uint_as_float((unsigned)(p1 >> 32));
        float v2 = __uint_as_float((unsigned)(p2 >> 32));
        float v3 = __uint_as_float((unsigned)(p3 >> 32));
        uint2 u0 = *(const uint2*)(hbase + o0);
        uint2 u1 = *(const uint2*)(hbase + o1);
        uint2 u2 = *(const uint2*)(hbase + o2);
        uint2 u3 = *(const uint2*)(hbase + o3);
        float2 a0 = __half22float2(*(__half2*)&u0.x);
        float2 b0 = __half22float2(*(__half2*)&u0.y);
        float2 a1 = __half22float2(*(__half2*)&u1.x);
        float2 b1 = __half22float2(*(__half2*)&u1.y);
        float2 a2 = __half22float2(*(__half2*)&u2.x);
        float2 b2 = __half22float2(*(__half2*)&u2.y);
        float2 a3 = __half22float2(*(__half2*)&u3.x);
        float2 b3 = __half22float2(*(__half2*)&u3.y);
        acc.x = fmaf(v0, a0.x, acc.x); acc.y = fmaf(v0, a0.y, acc.y);
        acc.z = fmaf(v0, b0.x, acc.z); acc.w = fmaf(v0, b0.y, acc.w);
        acc.x = fmaf(v1, a1.x, acc.x); acc.y = fmaf(v1, a1.y, acc.y);
        acc.z = fmaf(v1, b1.x, acc.z); acc.w = fmaf(v1, b1.y, acc.w);
        acc.x = fmaf(v2, a2.x, acc.x); acc.y = fmaf(v2, a2.y, acc.y);
        acc.z = fmaf(v2, b2.x, acc.z); acc.w = fmaf(v2, b2.y, acc.w);
        acc.x = fmaf(v3, a3.x, acc.x); acc.y = fmaf(v3, a3.y, acc.y);
        acc.z = fmaf(v3, b3.x, acc.z); acc.w = fmaf(v3, b3.y, acc.w);
    }
    for (; i < e; i++) {
        unsigned long long p0 = __ldg(&g_cv[i]);
        unsigned o0 = (unsigned)p0;
        float v0 = __uint_as_float((unsigned)(p0 >> 32));
        uint2 u0 = *(const uint2*)(hbase + o0);
        float2 a0 = __half22float2(*(__half2*)&u0.x);
        float2 b0 = __half22float2(*(__half2*)&u0.y);
        acc.x = fmaf(v0, a0.x, acc.x); acc.y = fmaf(v0, a0.y, acc.y);
        acc.z = fmaf(v0, b0.x, acc.z); acc.w = fmaf(v0, b0.y, acc.w);
    }

    acc.x = fmaxf(acc.x, 0.f); acc.y = fmaxf(acc.y, 0.f);
    acc.z = fmaxf(acc.z, 0.f); acc.w = fmaxf(acc.w, 0.f);

    ((float4*)(out + (size_t)warp * UDIM))[lane] = acc;
}

// ============================================================================
// launch
// ============================================================================
extern "C" void kernel_launch(void* const* d_in, const int* in_sizes, int n_in,
                              void* d_out, int out_size)
{
    const float* x      = (const float*)d_in[0];  // [M, 256]
    const float* kernel = (const float*)d_in[1];  // [256, 128]
    const int*   arows  = (const int*)d_in[2];    // [E]
    const int*   acols  = (const int*)d_in[3];    // [E]
    const float* avals  = (const float*)d_in[4];  // [E]
    float*       out    = (float*)d_out;          // [M, 128]

    const int M = in_sizes[0] / KDIM;
    const int E = in_sizes[2];
    const int gemm_nb = (M + 127) / 128;

    // 1) ONE fused kernel: CSR pipeline on 128 wave-1 blocks, GEMM overlapped
    fused_kernel<<<CSR_BLKS + gemm_nb, 256>>>(x, kernel, arows, acols, avals, M, E);

    // 2) segment reduce + relu (fp16 gathers, packed byte offsets)
    reduce_kernel<<<(M * 32 + 255) / 256, 256>>>(out, M);
}

// round 15
// speedup vs baseline: 2.0527x; 1.1324x over previous
#include <cuda_runtime.h>
#include <cuda_bf16.h>
#include <cuda_fp16.h>
#include <cstdint>

// Problem constants (fixed by the dataset)
#define KDIM 256      // IN_DIM
#define UDIM 128      // UNITS
#define MAX_NODES 100000
#define MAX_EDGES 3200000

#define CSR_BLKS 96

// ---------------- device scratch (static globals: no runtime alloc) ----------
__device__ __half             g_h[(size_t)MAX_NODES * UDIM];   // 25.6 MB (fp16)
__device__ int                g_cnt[MAX_NODES];                // zero-init; self-zeroing
__device__ int                g_off[MAX_NODES + 1];
__device__ int                g_cur[MAX_NODES];
__device__ int                g_bsum[256];
__device__ unsigned long long g_cv[MAX_EDGES];                 // packed (byteoff, val)
__device__ int                g_bar[4];   // barrier counters (self-reset)
__device__ int                g_dep[4];   // depart counters (self-reset)

// ---------------- small helpers ----------------------------------------------
__device__ __forceinline__ uint32_t smem_u32(const void* p) {
    uint32_t a;
    asm("{ .reg .u64 t; cvta.to.shared.u64 t, %1; cvt.u32.u64 %0, t; }"
        : "=r"(a) : "l"(p));
    return a;
}

__device__ __forceinline__ void ldmatrix_x4(uint32_t& r0, uint32_t& r1,
                                            uint32_t& r2, uint32_t& r3,
                                            uint32_t addr)
{
    asm volatile("ldmatrix.sync.aligned.m8n8.x4.shared.b16 {%0,%1,%2,%3}, [%4];"
                 : "=r"(r0), "=r"(r1), "=r"(r2), "=r"(r3) : "r"(addr));
}

__device__ __forceinline__ void mma_bf16(float* d, const uint32_t* a,
                                         uint32_t b0, uint32_t b1)
{
    asm volatile(
        "mma.sync.aligned.m16n8k16.row.col.f32.bf16.bf16.f32 "
        "{%0,%1,%2,%3}, {%4,%5,%6,%7}, {%8,%9}, {%0,%1,%2,%3};"
        : "+f"(d[0]), "+f"(d[1]), "+f"(d[2]), "+f"(d[3])
        : "r"(a[0]), "r"(a[1]), "r"(a[2]), "r"(a[3]), "r"(b0), "r"(b1));
}

__device__ __forceinline__ int ld_acq(const int* p) {
    int v;
    asm volatile("ld.acquire.gpu.b32 %0, [%1];" : "=r"(v) : "l"(p) : "memory");
    return v;
}

// Inter-block barrier among the 96 CSR blocks (wave-1 resident).
// Each call site uses a DISTINCT slot k (no back-to-back reuse).
__device__ __forceinline__ void csr_barrier(int k)
{
    __threadfence();
    __syncthreads();
    if (threadIdx.x == 0) {
        atomicAdd(&g_bar[k], 1);
        while (ld_acq(&g_bar[k]) < CSR_BLKS) __nanosleep(128);
        int d = atomicAdd(&g_dep[k], 1);
        if (d == CSR_BLKS - 1) {
            atomicExch(&g_dep[k], 0);
            atomicExch(&g_bar[k], 0);
        }
    }
    __syncthreads();
}

// ============================================================================
// FUSED kernel (round-9 structure, verbatim; scatter packs byte offsets):
//   blocks [0, CSR_BLKS):          hist -> bar0 -> scan -> bar1 -> off write
//                                  -> bar2 -> grid-stride scatter
//   blocks [CSR_BLKS, +gemm_nb):   one GEMM tile (mma.sync bf16 hi/lo split)
// ============================================================================
#define PITCH 80

__global__ __launch_bounds__(256) void fused_kernel(
    const float* __restrict__ X, const float* __restrict__ W,
    const int* __restrict__ rows, const int* __restrict__ cols,
    const float* __restrict__ vals, int M, int E)
{
    __shared__ __align__(16) char sA_hi[128 * PITCH];
    __shared__ __align__(16) char sA_lo[128 * PITCH];
    __shared__ __align__(16) char sB_hi[128 * PITCH];
    __shared__ __align__(16) char sB_lo[128 * PITCH];
    __shared__ int wsum[8];

    const int tid = threadIdx.x;
    const int bid = blockIdx.x;

    if (bid < CSR_BLKS) {
        // ================= CSR role =================
        const int stride = CSR_BLKS * 256;

        // ---- phase 1: histogram (grid-stride)
        for (int i = bid * 256 + tid; i < E; i += stride)
            atomicAdd(&g_cnt[rows[i]], 1);

        csr_barrier(0);

        // ---- phase 2: distributed exclusive scan of g_cnt
        const int C   = (M + CSR_BLKS - 1) / CSR_BLKS;   // 1042
        const int IPT = (C + 255) >> 8;                  // 5 (<=8)
        const int bstart = bid * C;
        const int bend   = min(bstart + C, M);
        const int i0     = bstart + tid * IPT;

        int loc[8];
        int s = 0;
#pragma unroll 8
        for (int j = 0; j < 8; j++) {
            int i = i0 + j;
            int v = (j < IPT && i < bend) ? g_cnt[i] : 0;
            loc[j] = v;
            s += v;
        }
        const int lane = tid & 31, w = tid >> 5;
        int p = s;
#pragma unroll
        for (int off = 1; off < 32; off <<= 1) {
            int t2 = __shfl_up_sync(0xffffffffu, p, off);
            if (lane >= off) p += t2;
        }
        if (lane == 31) wsum[w] = p;
        __syncthreads();
        if (w == 0) {
            int q = (lane < 8) ? wsum[lane] : 0;
#pragma unroll
            for (int off = 1; off < 8; off <<= 1) {
                int t2 = __shfl_up_sync(0xffffffffu, q, off);
                if (lane >= off) q += t2;
            }
            if (lane < 8) wsum[lane] = q;
        }
        __syncthreads();
        int excl  = (p - s) + ((w > 0) ? wsum[w - 1] : 0);
        int total = wsum[7];
        if (tid == 0) g_bsum[bid] = total;

        csr_barrier(1);

        // block base = sum of totals of blocks < bid
        int* red = (int*)sA_hi;
        int v = (tid < bid) ? g_bsum[tid] : 0;   // bid <= 95 < 256
        red[tid] = v;
        __syncthreads();
#pragma unroll
        for (int st = 128; st > 0; st >>= 1) {
            if (tid < st) red[tid] += red[tid + st];
            __syncthreads();
        }
        int run = red[0] + excl;

        // write g_off (inclusive at i+1), g_cur (exclusive), self-zero g_cnt
#pragma unroll 8
        for (int j = 0; j < 8; j++) {
            int i = i0 + j;
            if (j < IPT && i < bend) {
                run += loc[j];
                g_off[i + 1] = run;
                g_cur[i]     = run - loc[j];
                g_cnt[i]     = 0;
            }
        }
        if (bid == 0 && tid == 0) g_off[0] = 0;

        csr_barrier(2);

        // ---- phase 3: scatter (grid-stride), pack byte offset (col*256)
        for (int i = bid * 256 + tid; i < E; i += stride) {
            int r = rows[i];
            int ppos = atomicAdd(&g_cur[r], 1);
            unsigned long long packed =
                (unsigned long long)((unsigned)cols[i] << 8) |
                ((unsigned long long)__float_as_uint(vals[i]) << 32);
            g_cv[ppos] = packed;
        }
        return;
    }

    // ================= GEMM role =================
    const int wid  = tid >> 5;
    const int lane = tid & 31;
    const int warpM = wid & 3;        // 4 groups of 32 rows
    const int warpN = wid >> 2;       // 2 groups of 64 cols
    const int block_row = (bid - CSR_BLKS) * 128;

    float acc[2][8][4];
#pragma unroll
    for (int mg = 0; mg < 2; mg++)
#pragma unroll
        for (int ng = 0; ng < 8; ng++)
#pragma unroll
            for (int q = 0; q < 4; q++) acc[mg][ng][q] = 0.0f;

    const int matIdx = lane >> 3;
    const int rowInMat = lane & 7;
    const int a_roff = rowInMat + (matIdx & 1) * 8;
    const int a_koff = (matIdx >> 1) * 8;
    const int b_noff = (matIdx >> 1) * 8 + rowInMat;
    const int b_koff = (matIdx & 1) * 8;

    const uint32_t sAhi = smem_u32(sA_hi);
    const uint32_t sAlo = smem_u32(sA_lo);
    const uint32_t sBhi = smem_u32(sB_hi);
    const uint32_t sBlo = smem_u32(sB_lo);

    const int ld_row  = tid >> 1;     // 0..127
    const int ld_half = tid & 1;      // 0/1 -> 16 elements each
    const int b_n  = tid >> 1;        // 0..127
    const int b_k0 = (tid & 1) * 16;  // 0/16

#pragma unroll 1
    for (int kc = 0; kc < KDIM; kc += 32) {
        // ---- A: load 16 fp32, split hi/lo, store bf16
        {
            int grow = block_row + ld_row;
            float f[16];
            if (grow < M) {
                const float4* xp = (const float4*)(X + (size_t)grow * KDIM + kc + ld_half * 16);
#pragma unroll
                for (int q = 0; q < 4; q++) {
                    float4 vv = xp[q];
                    f[q * 4 + 0] = vv.x; f[q * 4 + 1] = vv.y;
                    f[q * 4 + 2] = vv.z; f[q * 4 + 3] = vv.w;
                }
            } else {
#pragma unroll
                for (int q = 0; q < 16; q++) f[q] = 0.0f;
            }
            union { __nv_bfloat16 b[16]; uint4 u[2]; } hi, lo;
#pragma unroll
            for (int q = 0; q < 16; q++) {
                __nv_bfloat16 h = __float2bfloat16(f[q]);
                hi.b[q] = h;
                lo.b[q] = __float2bfloat16(f[q] - __bfloat162float(h));
            }
            char* pa = sA_hi + ld_row * PITCH + ld_half * 32;
            char* pl = sA_lo + ld_row * PITCH + ld_half * 32;
            *(uint4*)(pa)      = hi.u[0];
            *(uint4*)(pa + 16) = hi.u[1];
            *(uint4*)(pl)      = lo.u[0];
            *(uint4*)(pl + 16) = lo.u[1];
        }
        // ---- B: load W fp32 chunk, split hi/lo + transpose to K-major
        {
            union { __nv_bfloat16 b[16]; uint4 u[2]; } hi, lo;
#pragma unroll
            for (int j = 0; j < 16; j++) {
                float wv = W[(size_t)(kc + b_k0 + j) * UDIM + b_n];
                __nv_bfloat16 h = __float2bfloat16(wv);
                hi.b[j] = h;
                lo.b[j] = __float2bfloat16(wv - __bfloat162float(h));
            }
            char* ph = sB_hi + b_n * PITCH + b_k0 * 2;
            char* pl = sB_lo + b_n * PITCH + b_k0 * 2;
            *(uint4*)(ph)      = hi.u[0];
            *(uint4*)(ph + 16) = hi.u[1];
            *(uint4*)(pl)      = lo.u[0];
            *(uint4*)(pl + 16) = lo.u[1];
        }
        __syncthreads();

#pragma unroll
        for (int ks = 0; ks < 2; ks++) {
            const int k0 = ks * 16;
            uint32_t ah[2][4], al[2][4];
#pragma unroll
            for (int mg = 0; mg < 2; mg++) {
                int row = warpM * 32 + mg * 16 + a_roff;
                uint32_t off = (uint32_t)(row * PITCH + (k0 + a_koff) * 2);
                ldmatrix_x4(ah[mg][0], ah[mg][1], ah[mg][2], ah[mg][3], sAhi + off);
                ldmatrix_x4(al[mg][0], al[mg][1], al[mg][2], al[mg][3], sAlo + off);
            }
#pragma unroll
            for (int g = 0; g < 4; g++) {
                uint32_t bh4[4], bl4[4];
                int n = warpN * 64 + g * 16 + b_noff;
                uint32_t off = (uint32_t)(n * PITCH + (k0 + b_koff) * 2);
                ldmatrix_x4(bh4[0], bh4[1], bh4[2], bh4[3], sBhi + off);
                ldmatrix_x4(bl4[0], bl4[1], bl4[2], bl4[3], sBlo + off);
#pragma unroll
                for (int mg = 0; mg < 2; mg++) {
#pragma unroll
                    for (int sg = 0; sg < 2; sg++) {
                        float* a = acc[mg][g * 2 + sg];
                        mma_bf16(a, ah[mg], bh4[sg * 2], bh4[sg * 2 + 1]); // hi*hi
                        mma_bf16(a, al[mg], bh4[sg * 2], bh4[sg * 2 + 1]); // lo*hi
                        mma_bf16(a, ah[mg], bl4[sg * 2], bl4[sg * 2 + 1]); // hi*lo
                    }
                }
            }
        }
        __syncthreads();
    }

    // ---- epilogue: write h as fp16
    const int qrow = lane >> 2;          // 0..7
    const int qcol = (lane & 3) * 2;     // 0,2,4,6
#pragma unroll
    for (int mg = 0; mg < 2; mg++) {
#pragma unroll
        for (int ng = 0; ng < 8; ng++) {
            int col = warpN * 64 + ng * 8 + qcol;
            int r0 = block_row + warpM * 32 + mg * 16 + qrow;
            if (r0 < M)
                *(__half2*)(g_h + (size_t)r0 * UDIM + col) =
                    __floats2half2_rn(acc[mg][ng][0], acc[mg][ng][1]);
            int r1 = r0 + 8;
            if (r1 < M)
                *(__half2*)(g_h + (size_t)r1 * UDIM + col) =
                    __floats2half2_rn(acc[mg][ng][2], acc[mg][ng][3]);
        }
    }
}

// ============================================================================
// Segment reduce: one warp per output row, fp16 h gathers via packed byte
// offsets (no per-edge address multiply), fp32 accum, relu epilogue
// ============================================================================
__global__ void reduce_kernel(float* __restrict__ out, int M)
{
    int warp = (blockIdx.x * blockDim.x + threadIdx.x) >> 5;
    int lane = threadIdx.x & 31;
    if (warp >= M) return;

    int s = g_off[warp];
    int e = g_off[warp + 1];

    const char* hbase = (const char*)g_h + lane * 8;   // lane's 8-byte column slot

    float4 acc = make_float4(0.f, 0.f, 0.f, 0.f);
    int i = s;
    for (; i + 3 < e; i += 4) {
        unsigned long long p0 = __ldg(&g_cv[i]);
        unsigned long long p1 = __ldg(&g_cv[i + 1]);
        unsigned long long p2 = __ldg(&g_cv[i + 2]);
        unsigned long long p3 = __ldg(&g_cv[i + 3]);
        unsigned o0 = (unsigned)p0, o1 = (unsigned)p1;
        unsigned o2 = (unsigned)p2, o3 = (unsigned)p3;
        float v0 = __uint_as_float((unsigned)(p0 >> 32));
        float v1 = __uint_as_float((unsigned)(p1 >> 32));
        float v2 = __uint_as_float((unsigned)(p2 >> 32));
        float v3 = __uint_as_float((unsigned)(p3 >> 32));
        uint2 u0 = *(const uint2*)(hbase + o0);
        uint2 u1 = *(const uint2*)(hbase + o1);
        uint2 u2 = *(const uint2*)(hbase + o2);
        uint2 u3 = *(const uint2*)(hbase + o3);
        float2 a0 = __half22float2(*(__half2*)&u0.x);
        float2 b0 = __half22float2(*(__half2*)&u0.y);
        float2 a1 = __half22float2(*(__half2*)&u1.x);
        float2 b1 = __half22float2(*(__half2*)&u1.y);
        float2 a2 = __half22float2(*(__half2*)&u2.x);
        float2 b2 = __half22float2(*(__half2*)&u2.y);
        float2 a3 = __half22float2(*(__half2*)&u3.x);
        float2 b3 = __half22float2(*(__half2*)&u3.y);
        acc.x = fmaf(v0, a0.x, acc.x); acc.y = fmaf(v0, a0.y, acc.y);
        acc.z = fmaf(v0, b0.x, acc.z); acc.w = fmaf(v0, b0.y, acc.w);
        acc.x = fmaf(v1, a1.x, acc.x); acc.y = fmaf(v1, a1.y, acc.y);
        acc.z = fmaf(v1, b1.x, acc.z); acc.w = fmaf(v1, b1.y, acc.w);
        acc.x = fmaf(v2, a2.x, acc.x); acc.y = fmaf(v2, a2.y, acc.y);
        acc.z = fmaf(v2, b2.x, acc.z); acc.w = fmaf(v2, b2.y, acc.w);
        acc.x = fmaf(v3, a3.x, acc.x); acc.y = fmaf(v3, a3.y, acc.y);
        acc.z = fmaf(v3, b3.x, acc.z); acc.w = fmaf(v3, b3.y, acc.w);
    }
    for (; i < e; i++) {
        unsigned long long p0 = __ldg(&g_cv[i]);
        unsigned o0 = (unsigned)p0;
        float v0 = __uint_as_float((unsigned)(p0 >> 32));
        uint2 u0 = *(const uint2*)(hbase + o0);
        float2 a0 = __half22float2(*(__half2*)&u0.x);
        float2 b0 = __half22float2(*(__half2*)&u0.y);
        acc.x = fmaf(v0, a0.x, acc.x); acc.y = fmaf(v0, a0.y, acc.y);
        acc.z = fmaf(v0, b0.x, acc.z); acc.w = fmaf(v0, b0.y, acc.w);
    }

    acc.x = fmaxf(acc.x, 0.f); acc.y = fmaxf(acc.y, 0.f);
    acc.z = fmaxf(acc.z, 0.f); acc.w = fmaxf(acc.w, 0.f);

    ((float4*)(out + (size_t)warp * UDIM))[lane] = acc;
}

// ============================================================================
// launch
// ============================================================================
extern "C" void kernel_launch(void* const* d_in, const int* in_sizes, int n_in,
                              void* d_out, int out_size)
{
    const float* x      = (const float*)d_in[0];  // [M, 256]
    const float* kernel = (const float*)d_in[1];  // [256, 128]
    const int*   arows  = (const int*)d_in[2];    // [E]
    const int*   acols  = (const int*)d_in[3];    // [E]
    const float* avals  = (const float*)d_in[4];  // [E]
    float*       out    = (float*)d_out;          // [M, 128]

    const int M = in_sizes[0] / KDIM;
    const int E = in_sizes[2];
    const int gemm_nb = (M + 127) / 128;

    // 1) ONE fused kernel: CSR pipeline on 96 wave-1 blocks (round-9 exact),
    //    GEMM overlapped; scatter packs byte offsets for the reduce
    fused_kernel<<<CSR_BLKS + gemm_nb, 256>>>(x, kernel, arows, acols, avals, M, E);

    // 2) segment reduce + relu (fp16 gathers, packed byte offsets)
    reduce_kernel<<<(M * 32 + 255) / 256, 256>>>(out, M);
}

// round 16
// speedup vs baseline: 2.4409x; 1.1891x over previous
#include <cuda_runtime.h>
#include <cuda_bf16.h>
#include <cuda_fp16.h>
#include <cstdint>

// Problem constants (fixed by the dataset)
#define KDIM 256      // IN_DIM
#define UDIM 128      // UNITS
#define MAX_NODES 100000
#define MAX_EDGES 3200000

#define CSR_BLKS 96

// ---------------- device scratch (static globals: no runtime alloc) ----------
__device__ __half             g_h[(size_t)MAX_NODES * UDIM];   // 25.6 MB (fp16)
__device__ int                g_cnt[MAX_NODES];                // zero-init; self-zeroing
__device__ int                g_off[MAX_NODES + 1];
__device__ int                g_cur[MAX_NODES];
__device__ int                g_bsum[256];
__device__ unsigned long long g_cv[MAX_EDGES];                 // packed (byteoff, val)
__device__ int                g_bar[4];   // barrier counters (self-reset)
__device__ int                g_dep[4];   // depart counters (self-reset)

// ---------------- small helpers ----------------------------------------------
__device__ __forceinline__ uint32_t smem_u32(const void* p) {
    uint32_t a;
    asm("{ .reg .u64 t; cvta.to.shared.u64 t, %1; cvt.u32.u64 %0, t; }"
        : "=r"(a) : "l"(p));
    return a;
}

__device__ __forceinline__ void ldmatrix_x4(uint32_t& r0, uint32_t& r1,
                                            uint32_t& r2, uint32_t& r3,
                                            uint32_t addr)
{
    asm volatile("ldmatrix.sync.aligned.m8n8.x4.shared.b16 {%0,%1,%2,%3}, [%4];"
                 : "=r"(r0), "=r"(r1), "=r"(r2), "=r"(r3) : "r"(addr));
}

__device__ __forceinline__ void mma_bf16(float* d, const uint32_t* a,
                                         uint32_t b0, uint32_t b1)
{
    asm volatile(
        "mma.sync.aligned.m16n8k16.row.col.f32.bf16.bf16.f32 "
        "{%0,%1,%2,%3}, {%4,%5,%6,%7}, {%8,%9}, {%0,%1,%2,%3};"
        : "+f"(d[0]), "+f"(d[1]), "+f"(d[2]), "+f"(d[3])
        : "r"(a[0]), "r"(a[1]), "r"(a[2]), "r"(a[3]), "r"(b0), "r"(b1));
}

__device__ __forceinline__ int ld_acq(const int* p) {
    int v;
    asm volatile("ld.acquire.gpu.b32 %0, [%1];" : "=r"(v) : "l"(p) : "memory");
    return v;
}

// Inter-block barrier among the 96 CSR blocks (wave-1 resident).
// Each call site uses a DISTINCT slot k (no back-to-back reuse).
__device__ __forceinline__ void csr_barrier(int k)
{
    __threadfence();
    __syncthreads();
    if (threadIdx.x == 0) {
        atomicAdd(&g_bar[k], 1);
        while (ld_acq(&g_bar[k]) < CSR_BLKS) __nanosleep(128);
        int d = atomicAdd(&g_dep[k], 1);
        if (d == CSR_BLKS - 1) {
            atomicExch(&g_dep[k], 0);
            atomicExch(&g_bar[k], 0);
        }
    }
    __syncthreads();
}

// ============================================================================
// FUSED kernel (round-9 structure AND round-9 GEMM inner loop, verbatim;
// scatter packs byte offsets for the reduce):
//   blocks [0, CSR_BLKS):          hist -> bar0 -> scan -> bar1 -> off write
//                                  -> bar2 -> grid-stride scatter
//   blocks [CSR_BLKS, +gemm_nb):   one GEMM tile (mma.sync bf16 hi/lo split)
// ============================================================================
#define PITCH 80

__global__ __launch_bounds__(256) void fused_kernel(
    const float* __restrict__ X, const float* __restrict__ W,
    const int* __restrict__ rows, const int* __restrict__ cols,
    const float* __restrict__ vals, int M, int E)
{
    __shared__ __align__(16) char sA_hi[128 * PITCH];
    __shared__ __align__(16) char sA_lo[128 * PITCH];
    __shared__ __align__(16) char sB_hi[128 * PITCH];
    __shared__ __align__(16) char sB_lo[128 * PITCH];
    __shared__ int wsum[8];

    const int tid = threadIdx.x;
    const int bid = blockIdx.x;

    if (bid < CSR_BLKS) {
        // ================= CSR role =================
        const int stride = CSR_BLKS * 256;

        // ---- phase 1: histogram (grid-stride)
        for (int i = bid * 256 + tid; i < E; i += stride)
            atomicAdd(&g_cnt[rows[i]], 1);

        csr_barrier(0);

        // ---- phase 2: distributed exclusive scan of g_cnt
        const int C   = (M + CSR_BLKS - 1) / CSR_BLKS;   // 1042
        const int IPT = (C + 255) >> 8;                  // 5 (<=8)
        const int bstart = bid * C;
        const int bend   = min(bstart + C, M);
        const int i0     = bstart + tid * IPT;

        int loc[8];
        int s = 0;
#pragma unroll 8
        for (int j = 0; j < 8; j++) {
            int i = i0 + j;
            int v = (j < IPT && i < bend) ? g_cnt[i] : 0;
            loc[j] = v;
            s += v;
        }
        const int lane = tid & 31, w = tid >> 5;
        int p = s;
#pragma unroll
        for (int off = 1; off < 32; off <<= 1) {
            int t2 = __shfl_up_sync(0xffffffffu, p, off);
            if (lane >= off) p += t2;
        }
        if (lane == 31) wsum[w] = p;
        __syncthreads();
        if (w == 0) {
            int q = (lane < 8) ? wsum[lane] : 0;
#pragma unroll
            for (int off = 1; off < 8; off <<= 1) {
                int t2 = __shfl_up_sync(0xffffffffu, q, off);
                if (lane >= off) q += t2;
            }
            if (lane < 8) wsum[lane] = q;
        }
        __syncthreads();
        int excl  = (p - s) + ((w > 0) ? wsum[w - 1] : 0);
        int total = wsum[7];
        if (tid == 0) g_bsum[bid] = total;

        csr_barrier(1);

        // block base = sum of totals of blocks < bid
        int* red = (int*)sA_hi;
        int v = (tid < bid) ? g_bsum[tid] : 0;   // bid <= 95 < 256
        red[tid] = v;
        __syncthreads();
#pragma unroll
        for (int st = 128; st > 0; st >>= 1) {
            if (tid < st) red[tid] += red[tid + st];
            __syncthreads();
        }
        int run = red[0] + excl;

        // write g_off (inclusive at i+1), g_cur (exclusive), self-zero g_cnt
#pragma unroll 8
        for (int j = 0; j < 8; j++) {
            int i = i0 + j;
            if (j < IPT && i < bend) {
                run += loc[j];
                g_off[i + 1] = run;
                g_cur[i]     = run - loc[j];
                g_cnt[i]     = 0;
            }
        }
        if (bid == 0 && tid == 0) g_off[0] = 0;

        csr_barrier(2);

        // ---- phase 3: scatter (grid-stride), pack byte offset (col*256)
        for (int i = bid * 256 + tid; i < E; i += stride) {
            int r = rows[i];
            int ppos = atomicAdd(&g_cur[r], 1);
            unsigned long long packed =
                (unsigned long long)((unsigned)cols[i] << 8) |
                ((unsigned long long)__float_as_uint(vals[i]) << 32);
            g_cv[ppos] = packed;
        }
        return;
    }

    // ================= GEMM role =================
    const int wid  = tid >> 5;
    const int lane = tid & 31;
    const int warpM = wid & 3;        // 4 groups of 32 rows
    const int warpN = wid >> 2;       // 2 groups of 64 cols
    const int block_row = (bid - CSR_BLKS) * 128;

    float acc[2][8][4];
#pragma unroll
    for (int mg = 0; mg < 2; mg++)
#pragma unroll
        for (int ng = 0; ng < 8; ng++)
#pragma unroll
            for (int q = 0; q < 4; q++) acc[mg][ng][q] = 0.0f;

    const int matIdx = lane >> 3;
    const int rowInMat = lane & 7;
    const int a_roff = rowInMat + (matIdx & 1) * 8;
    const int a_koff = (matIdx >> 1) * 8;
    const int b_noff = (matIdx >> 1) * 8 + rowInMat;
    const int b_koff = (matIdx & 1) * 8;

    const uint32_t sAhi = smem_u32(sA_hi);
    const uint32_t sAlo = smem_u32(sA_lo);
    const uint32_t sBhi = smem_u32(sB_hi);
    const uint32_t sBlo = smem_u32(sB_lo);

    const int ld_row  = tid >> 1;     // 0..127
    const int ld_half = tid & 1;      // 0/1 -> 16 elements each
    const int b_n  = tid >> 1;        // 0..127
    const int b_k0 = (tid & 1) * 16;  // 0/16

#pragma unroll 1
    for (int kc = 0; kc < KDIM; kc += 32) {
        // ---- A: load 16 fp32, split hi/lo, store bf16
        {
            int grow = block_row + ld_row;
            float f[16];
            if (grow < M) {
                const float4* xp = (const float4*)(X + (size_t)grow * KDIM + kc + ld_half * 16);
#pragma unroll
                for (int q = 0; q < 4; q++) {
                    float4 vv = xp[q];
                    f[q * 4 + 0] = vv.x; f[q * 4 + 1] = vv.y;
                    f[q * 4 + 2] = vv.z; f[q * 4 + 3] = vv.w;
                }
            } else {
#pragma unroll
                for (int q = 0; q < 16; q++) f[q] = 0.0f;
            }
            union { __nv_bfloat16 b[16]; uint4 u[2]; } hi, lo;
#pragma unroll
            for (int q = 0; q < 16; q++) {
                __nv_bfloat16 h = __float2bfloat16(f[q]);
                hi.b[q] = h;
                lo.b[q] = __float2bfloat16(f[q] - __bfloat162float(h));
            }
            char* pa = sA_hi + ld_row * PITCH + ld_half * 32;
            char* pl = sA_lo + ld_row * PITCH + ld_half * 32;
            *(uint4*)(pa)      = hi.u[0];
            *(uint4*)(pa + 16) = hi.u[1];
            *(uint4*)(pl)      = lo.u[0];
            *(uint4*)(pl + 16) = lo.u[1];
        }
        // ---- B: load W fp32 chunk, split hi/lo + transpose to K-major
        {
            union { __nv_bfloat16 b[16]; uint4 u[2]; } hi, lo;
#pragma unroll
            for (int j = 0; j < 16; j++) {
                float wv = W[(size_t)(kc + b_k0 + j) * UDIM + b_n];
                __nv_bfloat16 h = __float2bfloat16(wv);
                hi.b[j] = h;
                lo.b[j] = __float2bfloat16(wv - __bfloat162float(h));
            }
            char* ph = sB_hi + b_n * PITCH + b_k0 * 2;
            char* pl = sB_lo + b_n * PITCH + b_k0 * 2;
            *(uint4*)(ph)      = hi.u[0];
            *(uint4*)(ph + 16) = hi.u[1];
            *(uint4*)(pl)      = lo.u[0];
            *(uint4*)(pl + 16) = lo.u[1];
        }
        __syncthreads();

#pragma unroll
        for (int ks = 0; ks < 2; ks++) {
            const int k0 = ks * 16;
            // ---- A fragments (hi & lo), 2 m16 blocks — loaded upfront
            uint32_t ah[2][4], al[2][4];
#pragma unroll
            for (int mg = 0; mg < 2; mg++) {
                int row = warpM * 32 + mg * 16 + a_roff;
                uint32_t off = (uint32_t)(row * PITCH + (k0 + a_koff) * 2);
                ldmatrix_x4(ah[mg][0], ah[mg][1], ah[mg][2], ah[mg][3], sAhi + off);
                ldmatrix_x4(al[mg][0], al[mg][1], al[mg][2], al[mg][3], sAlo + off);
            }
            // ---- B fragments (hi & lo), ALL 4 n16 groups loaded upfront
            uint32_t bh[4][4], bl[4][4];
#pragma unroll
            for (int g = 0; g < 4; g++) {
                int n = warpN * 64 + g * 16 + b_noff;
                uint32_t off = (uint32_t)(n * PITCH + (k0 + b_koff) * 2);
                ldmatrix_x4(bh[g][0], bh[g][1], bh[g][2], bh[g][3], sBhi + off);
                ldmatrix_x4(bl[g][0], bl[g][1], bl[g][2], bl[g][3], sBlo + off);
            }
            // ---- MMAs: 3 terms x 2 mg x 8 ng
#pragma unroll
            for (int mg = 0; mg < 2; mg++) {
#pragma unroll
                for (int ng = 0; ng < 8; ng++) {
                    int g = ng >> 1, sgl = (ng & 1) * 2;
                    mma_bf16(acc[mg][ng], ah[mg], bh[g][sgl], bh[g][sgl + 1]); // hi*hi
                    mma_bf16(acc[mg][ng], al[mg], bh[g][sgl], bh[g][sgl + 1]); // lo*hi
                    mma_bf16(acc[mg][ng], ah[mg], bl[g][sgl], bl[g][sgl + 1]); // hi*lo
                }
            }
        }
        __syncthreads();
    }

    // ---- epilogue: write h as fp16
    const int qrow = lane >> 2;          // 0..7
    const int qcol = (lane & 3) * 2;     // 0,2,4,6
#pragma unroll
    for (int mg = 0; mg < 2; mg++) {
#pragma unroll
        for (int ng = 0; ng < 8; ng++) {
            int col = warpN * 64 + ng * 8 + qcol;
            int r0 = block_row + warpM * 32 + mg * 16 + qrow;
            if (r0 < M)
                *(__half2*)(g_h + (size_t)r0 * UDIM + col) =
                    __floats2half2_rn(acc[mg][ng][0], acc[mg][ng][1]);
            int r1 = r0 + 8;
            if (r1 < M)
                *(__half2*)(g_h + (size_t)r1 * UDIM + col) =
                    __floats2half2_rn(acc[mg][ng][2], acc[mg][ng][3]);
        }
    }
}

// ============================================================================
// Segment reduce: one warp per output row, fp16 h gathers via packed byte
// offsets (no per-edge address multiply), fp32 accum, relu epilogue
// ============================================================================
__global__ void reduce_kernel(float* __restrict__ out, int M)
{
    int warp = (blockIdx.x * blockDim.x + threadIdx.x) >> 5;
    int lane = threadIdx.x & 31;
    if (warp >= M) return;

    int s = g_off[warp];
    int e = g_off[warp + 1];

    const char* hbase = (const char*)g_h + lane * 8;   // lane's 8-byte column slot

    float4 acc = make_float4(0.f, 0.f, 0.f, 0.f);
    int i = s;
    for (; i + 3 < e; i += 4) {
        unsigned long long p0 = __ldg(&g_cv[i]);
        unsigned long long p1 = __ldg(&g_cv[i + 1]);
        unsigned long long p2 = __ldg(&g_cv[i + 2]);
        unsigned long long p3 = __ldg(&g_cv[i + 3]);
        unsigned o0 = (unsigned)p0, o1 = (unsigned)p1;
        unsigned o2 = (unsigned)p2, o3 = (unsigned)p3;
        float v0 = __uint_as_float((unsigned)(p0 >> 32));
        float v1 = __uint_as_float((unsigned)(p1 >> 32));
        float v2 = __uint_as_float((unsigned)(p2 >> 32));
        float v3 = __uint_as_float((unsigned)(p3 >> 32));
        uint2 u0 = *(const uint2*)(hbase + o0);
        uint2 u1 = *(const uint2*)(hbase + o1);
        uint2 u2 = *(const uint2*)(hbase + o2);
        uint2 u3 = *(const uint2*)(hbase + o3);
        float2 a0 = __half22float2(*(__half2*)&u0.x);
        float2 b0 = __half22float2(*(__half2*)&u0.y);
        float2 a1 = __half22float2(*(__half2*)&u1.x);
        float2 b1 = __half22float2(*(__half2*)&u1.y);
        float2 a2 = __half22float2(*(__half2*)&u2.x);
        float2 b2 = __half22float2(*(__half2*)&u2.y);
        float2 a3 = __half22float2(*(__half2*)&u3.x);
        float2 b3 = __half22float2(*(__half2*)&u3.y);
        acc.x = fmaf(v0, a0.x, acc.x); acc.y = fmaf(v0, a0.y, acc.y);
        acc.z = fmaf(v0, b0.x, acc.z); acc.w = fmaf(v0, b0.y, acc.w);
        acc.x = fmaf(v1, a1.x, acc.x); acc.y = fmaf(v1, a1.y, acc.y);
        acc.z = fmaf(v1, b1.x, acc.z); acc.w = fmaf(v1, b1.y, acc.w);
        acc.x = fmaf(v2, a2.x, acc.x); acc.y = fmaf(v2, a2.y, acc.y);
        acc.z = fmaf(v2, b2.x, acc.z); acc.w = fmaf(v2, b2.y, acc.w);
        acc.x = fmaf(v3, a3.x, acc.x); acc.y = fmaf(v3, a3.y, acc.y);
        acc.z = fmaf(v3, b3.x, acc.z); acc.w = fmaf(v3, b3.y, acc.w);
    }
    for (; i < e; i++) {
        unsigned long long p0 = __ldg(&g_cv[i]);
        unsigned o0 = (unsigned)p0;
        float v0 = __uint_as_float((unsigned)(p0 >> 32));
        uint2 u0 = *(const uint2*)(hbase + o0);
        float2 a0 = __half22float2(*(__half2*)&u0.x);
        float2 b0 = __half22float2(*(__half2*)&u0.y);
        acc.x = fmaf(v0, a0.x, acc.x); acc.y = fmaf(v0, a0.y, acc.y);
        acc.z = fmaf(v0, b0.x, acc.z); acc.w = fmaf(v0, b0.y, acc.w);
    }

    acc.x = fmaxf(acc.x, 0.f); acc.y = fmaxf(acc.y, 0.f);
    acc.z = fmaxf(acc.z, 0.f); acc.w = fmaxf(acc.w, 0.f);

    ((float4*)(out + (size_t)warp * UDIM))[lane] = acc;
}

// ============================================================================
// launch
// ============================================================================
extern "C" void kernel_launch(void* const* d_in, const int* in_sizes, int n_in,
                              void* d_out, int out_size)
{
    const float* x      = (const float*)d_in[0];  // [M, 256]
    const float* kernel = (const float*)d_in[1];  // [256, 128]
    const int*   arows  = (const int*)d_in[2];    // [E]
    const int*   acols  = (const int*)d_in[3];    // [E]
    const float* avals  = (const float*)d_in[4];  // [E]
    float*       out    = (float*)d_out;          // [M, 128]

    const int M = in_sizes[0] / KDIM;
    const int E = in_sizes[2];
    const int gemm_nb = (M + 127) / 128;

    // 1) ONE fused kernel: CSR pipeline on 96 wave-1 blocks, GEMM overlapped
    //    (round-9 exact GEMM inner loop with upfront fragment loads)
    fused_kernel<<<CSR_BLKS + gemm_nb, 256>>>(x, kernel, arows, acols, avals, M, E);

    // 2) segment reduce + relu (fp16 gathers, packed byte offsets)
    reduce_kernel<<<(M * 32 + 255) / 256, 256>>>(out, M);
}